// round 6
// baseline (speedup 1.0000x reference)
#include <cuda_runtime.h>

// transforms_blue: per-pixel BGR2GRAY + conditional channel boost, fp32 in/out.
// Layout [B=64, C=3, H=512, W=512]; channel plane = 512*512 = 262144 floats.
// Persistent single-wave grid-stride form: no wave transitions, loop-pipelined
// independent loads, streaming L2 hints, fully coalesced 128-bit accesses.

#define PLANE   262144          // floats per channel plane (512*512)
#define PLANE4  (PLANE / 4)     // 65536 float4 per plane
#define BATCH_STRIDE (3 * PLANE)
#define NPIX4   (64 * PLANE4)   // 4,194,304 float4 pixel-groups
#define THREADS 128
#define NBLOCKS (148 * 16)      // one full wave at occ=16 CTAs/SM (64 warps? no: 16*4=64… cap 32) — see launch

__device__ __forceinline__ float gray_of(float x0, float x1, float x2) {
    float u0 = floorf(x0 * 255.0f);
    float u1 = floorf(x1 * 255.0f);
    float u2 = floorf(x2 * 255.0f);
    return rintf(0.114f * u0 + 0.587f * u1 + 0.299f * u2);  // jnp.round = half-even
}

__device__ __forceinline__ void px(float a, float b, float c,
                                   float& r0, float& r1, float& r2) {
    const float inv255 = 1.0f / 255.0f;
    float gy = gray_of(a, b, c);
    bool m = gy < 128.0f;
    r0 = (m ? gy + 60.0f : gy) * inv255;
    r1 = (m ? gy + 10.0f : gy) * inv255;
    r2 = gy * inv255;
}

__global__ void __launch_bounds__(THREADS) transforms_blue_kernel(
    const float* __restrict__ in, float* __restrict__ out, unsigned nthreads)
{
    unsigned g = blockIdx.x * THREADS + threadIdx.x;

    #pragma unroll 2
    for (; g < NPIX4; g += nthreads) {
        unsigned b    = g >> 16;            // g / PLANE4
        unsigned off  = (g & 65535u) * 4;   // float offset within plane
        unsigned base = b * BATCH_STRIDE + off;

        const float4 v0 = __ldcs(reinterpret_cast<const float4*>(in + base));
        const float4 v1 = __ldcs(reinterpret_cast<const float4*>(in + base + PLANE));
        const float4 v2 = __ldcs(reinterpret_cast<const float4*>(in + base + 2 * PLANE));

        float4 o0, o1, o2;
        px(v0.x, v1.x, v2.x, o0.x, o1.x, o2.x);
        px(v0.y, v1.y, v2.y, o0.y, o1.y, o2.y);
        px(v0.z, v1.z, v2.z, o0.z, o1.z, o2.z);
        px(v0.w, v1.w, v2.w, o0.w, o1.w, o2.w);

        __stcs(reinterpret_cast<float4*>(out + base),             o0);
        __stcs(reinterpret_cast<float4*>(out + base + PLANE),     o1);
        __stcs(reinterpret_cast<float4*>(out + base + 2 * PLANE), o2);
    }
}

extern "C" void kernel_launch(void* const* d_in, const int* in_sizes, int n_in,
                              void* d_out, int out_size) {
    const float* in = (const float*)d_in[0];
    float* out = (float*)d_out;
    // One wave: 148 SMs (sm_100a B200) x 8 CTAs of 128 threads = 32 warps/SM
    // (occupancy-exact at 24 regs, 0 smem).
    const int blocks = 148 * 8;   // 1184 CTAs, ~28 groups per thread
    const unsigned nthreads = blocks * THREADS;
    transforms_blue_kernel<<<blocks, THREADS>>>(in, out, nthreads);
}